// round 14
// baseline (speedup 1.0000x reference)
#include <cuda_runtime.h>
#include <cstdint>

#define BB 4
#define DD 256
#define NN 4096
#define MM 4096
#define TN 128            // n rows per CTA
#define TM 32             // m cols per tile
#define NMT (MM / TM)     // 128 m-tiles
#define NSTAGE 3
#define L2E 1.4426950408889634f
#define LOSC 254.0f
#define INV_LOSC (1.0f / 254.0f)

#define ROW_BYTES 256     // 256 s8, XOR-swizzled 16B chunks (conflict-free for ldmatrix)
#define B_HALF (TM * ROW_BYTES)          // 8192
#define B_BLOB (2 * B_HALF)              // 16384 (hi then lo)
#define A_HALF (TN * ROW_BYTES)          // 32768

__device__ __align__(16) unsigned char g_B[BB * NMT * B_BLOB];  // 8MB
__device__ __align__(16) float4 g_ytg[BB * MM];                 // (yy*log2e, t0,t1,t2)
__device__ __align__(16) float g_sb[BB * MM];                   // B col scale (s_qb)
__device__ __align__(16) float g_sa[BB * NN];                   // A row scale (2*L2E*s_qa)
__device__ __align__(16) float g_sainv[BB * NN];                // 1/s_qa for quantization

// ---------------- helpers ----------------
__device__ __forceinline__ uint32_t smem_u32(const void* p) {
    uint32_t a;
    asm("{ .reg .u64 t; cvta.to.shared.u64 t, %1; cvt.u32.u64 %0, t; }"
        : "=r"(a) : "l"(p));
    return a;
}

#define MBARRIER_INIT(mbar, cnt) \
    asm volatile("mbarrier.init.shared.b64 [%0], %1;" \
                 :: "r"((uint32_t)(mbar)), "r"((uint32_t)(cnt)) : "memory")
#define MBARRIER_EXPECT_TX(mbar, bytes) \
    asm volatile("mbarrier.arrive.expect_tx.shared.b64 _, [%0], %1;" \
                 :: "r"((uint32_t)(mbar)), "r"((uint32_t)(bytes)) : "memory")
#define MBARRIER_ARRIVE(mbar) \
    asm volatile("mbarrier.arrive.shared.b64 _, [%0];" \
                 :: "r"((uint32_t)(mbar)) : "memory")
#define MBARRIER_WAIT_PARITY(mbar, ph) do {                                    \
    uint32_t _m = (uint32_t)(mbar); uint32_t _p = (uint32_t)(ph);               \
    asm volatile(                                                               \
        "{\n\t.reg .pred P1;\n\t"                                               \
        "WL_%=:\n\t"                                                            \
        "mbarrier.try_wait.parity.acquire.cta.shared::cta.b64 P1, [%0], %1, 0x989680;\n\t" \
        "@P1 bra.uni WD_%=;\n\t"                                                \
        "bra.uni WL_%=;\n\t"                                                    \
        "WD_%=:\n\t}"                                                           \
        :: "r"(_m), "r"(_p) : "memory");                                        \
} while (0)

__device__ __forceinline__ void bulk_g2s(uint32_t dst_smem, const void* src,
                                         uint32_t bytes, uint32_t mbar) {
    asm volatile(
        "cp.async.bulk.shared::cluster.global.mbarrier::complete_tx::bytes [%0], [%1], %2, [%3];"
        :: "r"(dst_smem), "l"(src), "r"(bytes), "r"(mbar) : "memory");
}

__device__ __forceinline__ float ex2(float x) {
    float r;
    asm("ex2.approx.f32 %0, %1;" : "=f"(r) : "f"(x));
    return r;
}

#define LDSM_X4(r, addr) \
    asm volatile("ldmatrix.sync.aligned.m8n8.x4.shared.b16 {%0,%1,%2,%3}, [%4];" \
                 : "=r"((r)[0]), "=r"((r)[1]), "=r"((r)[2]), "=r"((r)[3]) \
                 : "r"(addr))

__device__ __forceinline__ void mma_s8(int (&c)[4],
                                       const uint32_t (&a)[4],
                                       uint32_t b0, uint32_t b1) {
    asm volatile(
        "mma.sync.aligned.m16n8k32.row.col.s32.s8.s8.s32 "
        "{%0,%1,%2,%3}, {%4,%5,%6,%7}, {%8,%9}, {%0,%1,%2,%3};"
        : "+r"(c[0]), "+r"(c[1]), "+r"(c[2]), "+r"(c[3])
        : "r"(a[0]), "r"(a[1]), "r"(a[2]), "r"(a[3]), "r"(b0), "r"(b1));
}

// quantize v/s into hi (int8) + lo (int8, scaled by LOSC)
__device__ __forceinline__ void quant2(float q, int& hi, int& lo) {
    hi = __float2int_rn(q);
    lo = __float2int_rn((q - (float)hi) * LOSC);
}

// ======= Kernel 0: per-row A scales =======
__global__ void __launch_bounds__(256)
sa_kernel(const float* __restrict__ src_emb) {
    int b = blockIdx.y;
    int n = blockIdx.x * 256 + threadIdx.x;
    const float* p = src_emb + (size_t)b * DD * NN + n;
    float mx = 0.f;
#pragma unroll 8
    for (int d = 0; d < DD; ++d) mx = fmaxf(mx, fabsf(p[(size_t)d * NN]));
    g_sa[b * NN + n] = 2.0f * L2E * mx * (1.0f / 127.0f);
    g_sainv[b * NN + n] = 127.0f / mx;
}

// ======= Kernel 1: tgt_emb -> swizzled s8 hi/lo blobs + ytg + sb =======
#define CV_PAD 264
#define CONVB_SMEM ((TM * CV_PAD + 3 * TM) * 4)

__global__ void __launch_bounds__(256)
convB_kernel(const float* __restrict__ tgt_emb, const float* __restrict__ tgt) {
    extern __shared__ float cs[];          // [TM][CV_PAD] transpose stage
    float* syy   = cs + TM * CV_PAD;       // [TM]
    float* sbv   = syy + TM;               // [TM] scale
    float* sbinv = sbv + TM;               // [TM] 1/scale
    const int tid = threadIdx.x;
    const int b = blockIdx.y, mt = blockIdx.x, m0 = mt * TM;

    const float* g = tgt_emb + (size_t)b * DD * MM + m0;
    for (int i = tid; i < DD * TM; i += 256) {
        int d = i >> 5, m = i & 31;
        cs[m * CV_PAD + d] = g[(size_t)d * MM + m];
    }
    __syncthreads();

    if (tid < TM) {
        float mx = 0.f, yy = 0.f;
        const float* p = cs + tid * CV_PAD;
#pragma unroll 8
        for (int d = 0; d < DD; ++d) {
            float v = p[d];
            yy += v * v;
            mx = fmaxf(mx, fabsf(v));
        }
        syy[tid] = yy;
        sbv[tid] = mx * (1.0f / 127.0f);
        sbinv[tid] = 127.0f / mx;
    }
    __syncthreads();

    unsigned char* outh = g_B + (size_t)(b * NMT + mt) * B_BLOB;
    unsigned char* outl = outh + B_HALF;

    for (int i = tid; i < TM * 32; i += 256) {   // task = (m-row, 8-byte group kg)
        int m = i >> 5, kg = i & 31;
        const float* p = cs + m * CV_PAD + kg * 8;
        float inv = sbinv[m];
        unsigned char hb[8], lb[8];
#pragma unroll
        for (int e = 0; e < 8; ++e) {
            int hi, lo;
            quant2(p[e] * inv, hi, lo);
            hb[e] = (unsigned char)hi;
            lb[e] = (unsigned char)lo;
        }
        // row 256B = 16 chunks of 16B; this task covers half-chunk (kg&1)
        int byte = m * ROW_BYTES + (((kg >> 1) ^ (m & 7)) << 4) + ((kg & 1) << 3);
        *(uint2*)(outh + byte) = *(uint2*)hb;
        *(uint2*)(outl + byte) = *(uint2*)lb;
    }
    __syncthreads();
    if (tid < TM) {
        int m = m0 + tid;
        float4 v;
        v.x = L2E * syy[tid];
        v.y = tgt[(size_t)b * 3 * MM + m];
        v.z = tgt[(size_t)b * 3 * MM + MM + m];
        v.w = tgt[(size_t)b * 3 * MM + 2 * MM + m];
        g_ytg[b * MM + m] = v;
        g_sb[b * MM + m] = sbv[tid];
    }
}

// ======= Kernel 2: fused IMMA GEMM, A-in-regs, 3-stage ring =======
// SMEM: mbar x3 @0..47, ytg 3x512 @64, sb 3x128 @1664, A @2048, B ring @67584
#define SM_YTG 64
#define SM_SB  1664
#define SM_A   2048
#define SM_B   (SM_A + 2 * A_HALF)              // 67584
#define SMEM_MAIN (SM_B + NSTAGE * B_BLOB)      // 116736
#define TX_BYTES (B_BLOB + 512 + 128)

struct RowState { float m, s, o0, o1, o2; };

__device__ __forceinline__ void row_update(RowState& st, const float (&lg)[8],
                                           const float4 (&yt)[8]) {
    float tmax = lg[0];
#pragma unroll
    for (int j = 1; j < 8; ++j) tmax = fmaxf(tmax, lg[j]);
    float nm = fmaxf(st.m, tmax);
    float corr = ex2(st.m - nm);
    st.m = nm;
    float ls = 0.f, a0 = 0.f, a1 = 0.f, a2 = 0.f;
#pragma unroll
    for (int j = 0; j < 8; ++j) {
        float p = ex2(lg[j] - nm);
        ls += p;
        a0 += p * yt[j].y;
        a1 += p * yt[j].z;
        a2 += p * yt[j].w;
    }
    st.s = st.s * corr + ls;
    st.o0 = st.o0 * corr + a0;
    st.o1 = st.o1 * corr + a1;
    st.o2 = st.o2 * corr + a2;
}

__device__ __forceinline__ void row_merge(RowState& st, int off) {
    float om = __shfl_xor_sync(0xffffffffu, st.m, off);
    float os = __shfl_xor_sync(0xffffffffu, st.s, off);
    float g0 = __shfl_xor_sync(0xffffffffu, st.o0, off);
    float g1 = __shfl_xor_sync(0xffffffffu, st.o1, off);
    float g2 = __shfl_xor_sync(0xffffffffu, st.o2, off);
    float nm = fmaxf(st.m, om);
    float ca = ex2(st.m - nm), cb = ex2(om - nm);
    st.m = nm;
    st.s = st.s * ca + os * cb;
    st.o0 = st.o0 * ca + g0 * cb;
    st.o1 = st.o1 * ca + g1 * cb;
    st.o2 = st.o2 * ca + g2 * cb;
}

__global__ void __launch_bounds__(256, 1)
corr_mma_kernel(const float* __restrict__ src_emb, float* __restrict__ out) {
    extern __shared__ __align__(16) unsigned char smraw[];
    const uint32_t sb = smem_u32(smraw);
    const int tid = threadIdx.x;
    const int wid = tid >> 5;
    const int lane = tid & 31;
    const int b = blockIdx.y;
    const int n0 = blockIdx.x * TN;

    if (tid == 0) {
#pragma unroll
        for (int s = 0; s < NSTAGE; ++s) {
            MBARRIER_INIT(sb + s * 16, 1);       // full
            MBARRIER_INIT(sb + s * 16 + 8, 8);   // empty: 8 warp arrivals
        }
    }
    __syncthreads();

    const unsigned char* gB = g_B + (size_t)b * NMT * B_BLOB;
    const float4* gY = g_ytg + b * MM;
    const float* gSB = g_sb + b * MM;

    // kick off loads for tiles 0..2
    if (tid == 0) {
#pragma unroll
        for (int s = 0; s < NSTAGE; ++s) {
            MBARRIER_EXPECT_TX(sb + s * 16, TX_BYTES);
            bulk_g2s(sb + SM_B + s * B_BLOB, gB + (size_t)s * B_BLOB, B_BLOB, sb + s * 16);
            bulk_g2s(sb + SM_YTG + s * 512, gY + s * TM, 512, sb + s * 16);
            bulk_g2s(sb + SM_SB + s * 128, gSB + s * TM, 128, sb + s * 16);
        }
    }

    // ---- quantize A (src_emb rows n0..n0+127) into SMEM s8 hi/lo ----
    {
        unsigned char* Ah = smraw + SM_A;
        unsigned char* Al = Ah + A_HALF;
        const float* gA = src_emb + (size_t)b * DD * NN + n0;
        const int n = tid & 127;
        const float inv = g_sainv[b * NN + n0 + n];
#pragma unroll 4
        for (int i = tid; i < DD * TN / 2; i += 256) {
            int dp = i >> 7;             // 0..127, covers d = 2dp, 2dp+1
            float v0 = gA[(size_t)(2 * dp) * NN + n];
            float v1 = gA[(size_t)(2 * dp + 1) * NN + n];
            int h0, l0, h1, l1;
            quant2(v0 * inv, h0, l0);
            quant2(v1 * inv, h1, l1);
            uint16_t hw = (uint16_t)((h0 & 0xff) | ((h1 & 0xff) << 8));
            uint16_t lw = (uint16_t)((l0 & 0xff) | ((l1 & 0xff) << 8));
            int byte = n * ROW_BYTES + (((dp >> 3) ^ (n & 7)) << 4) + ((2 * dp) & 15);
            *(uint16_t*)(Ah + byte) = hw;
            *(uint16_t*)(Al + byte) = lw;
        }
    }
    __syncthreads();

    // ---- A fragments -> registers (persistent across all 128 tiles) ----
    const int q = lane & 3;
    const int r = lane >> 2;
    const uint32_t rowA = wid * 16 + ((lane >> 3) & 1) * 8 + (lane & 7);
    const uint32_t aBase = sb + SM_A + rowA * ROW_BYTES;
    const uint32_t hcA = (uint32_t)(lane >> 4);       // 0/1: 16B chunk half
    const uint32_t rswA = rowA & 7;

    uint32_t ahr[8][4], alr[8][4];
#pragma unroll
    for (int s = 0; s < 8; ++s) {
        const uint32_t swA = ((2 * s + hcA) ^ rswA) << 4;
        LDSM_X4(ahr[s], aBase + swA);
        LDSM_X4(alr[s], aBase + swA + A_HALF);
    }

    // per-row A scales (rows wid*16+r and +8), includes 2*log2e
    const float sa0 = g_sa[b * NN + n0 + wid * 16 + r];
    const float sa1 = g_sa[b * NN + n0 + wid * 16 + r + 8];

    // B ldmatrix lane bases
    const uint32_t rB0 = (uint32_t)((lane >> 4) * 8 + (lane & 7));  // rows 0..15
    const uint32_t bBase0 = rB0 * ROW_BYTES;
    const uint32_t hcB = (uint32_t)((lane >> 3) & 1);
    const uint32_t rswB = rB0 & 7;

    RowState st0 = {-1e30f, 0.f, 0.f, 0.f, 0.f};
    RowState st1 = {-1e30f, 0.f, 0.f, 0.f, 0.f};

    const float4* ytg_s = (const float4*)(smraw + SM_YTG);
    const float* sb_s = (const float*)(smraw + SM_SB);

    int stage = 0, phase = 0;
    for (int t = 0; t < NMT; ++t) {
        MBARRIER_WAIT_PARITY(sb + stage * 16, phase);

        const uint32_t bb = sb + SM_B + stage * B_BLOB;

        int hh[4][4], xx[4][4];
#pragma unroll
        for (int j = 0; j < 4; ++j)
#pragma unroll
            for (int e = 0; e < 4; ++e) { hh[j][e] = 0; xx[j][e] = 0; }

#pragma unroll
        for (int s = 0; s < 8; ++s) {
            const uint32_t swB = ((2 * s + hcB) ^ rswB) << 4;
            uint32_t bh[4], bh2[4], bl[4], bl2[4];
            LDSM_X4(bh, bb + bBase0 + swB);
            LDSM_X4(bh2, bb + bBase0 + swB + 16 * ROW_BYTES);
            LDSM_X4(bl, bb + bBase0 + swB + B_HALF);
            LDSM_X4(bl2, bb + bBase0 + swB + B_HALF + 16 * ROW_BYTES);
            // hi*hi
            mma_s8(hh[0], ahr[s], bh[0], bh[1]);
            mma_s8(hh[1], ahr[s], bh[2], bh[3]);
            mma_s8(hh[2], ahr[s], bh2[0], bh2[1]);
            mma_s8(hh[3], ahr[s], bh2[2], bh2[3]);
            // hi*lo -> cross
            mma_s8(xx[0], ahr[s], bl[0], bl[1]);
            mma_s8(xx[1], ahr[s], bl[2], bl[3]);
            mma_s8(xx[2], ahr[s], bl2[0], bl2[1]);
            mma_s8(xx[3], ahr[s], bl2[2], bl2[3]);
            // lo*hi -> cross
            mma_s8(xx[0], alr[s], bh[0], bh[1]);
            mma_s8(xx[1], alr[s], bh[2], bh[3]);
            mma_s8(xx[2], alr[s], bh2[0], bh2[1]);
            mma_s8(xx[3], alr[s], bh2[2], bh2[3]);
        }

        // grab this tile's (yy, t0..t2) and col scales before releasing buffer
        float4 yt[8];
        float sbc[8];
#pragma unroll
        for (int j = 0; j < 4; ++j)
#pragma unroll
            for (int e = 0; e < 2; ++e) {
                int c = j * 8 + q * 2 + e;
                yt[j * 2 + e] = ytg_s[stage * 32 + c];
                sbc[j * 2 + e] = sb_s[stage * 32 + c];
            }

        if (lane == 0) MBARRIER_ARRIVE(sb + stage * 16 + 8);  // warp done with buffer

        // producer: refill this stage for tile t+3 once all warps released it
        if (tid == 0 && t + NSTAGE < NMT) {
            MBARRIER_WAIT_PARITY(sb + stage * 16 + 8, phase);
            MBARRIER_EXPECT_TX(sb + stage * 16, TX_BYTES);
            bulk_g2s(sb + SM_B + stage * B_BLOB, gB + (size_t)(t + NSTAGE) * B_BLOB,
                     B_BLOB, sb + stage * 16);
            bulk_g2s(sb + SM_YTG + stage * 512, gY + (t + NSTAGE) * TM, 512,
                     sb + stage * 16);
            bulk_g2s(sb + SM_SB + stage * 128, gSB + (t + NSTAGE) * TM, 128,
                     sb + stage * 16);
        }

        // ---- dequant + per-thread online softmax (rows wid*16+r, +8) ----
        float l0[8], l1[8];
#pragma unroll
        for (int j = 0; j < 4; ++j)
#pragma unroll
            for (int e = 0; e < 2; ++e) {
                int jj = j * 2 + e;
                float f0 = (float)hh[j][e] + (float)xx[j][e] * INV_LOSC;
                float f1 = (float)hh[j][2 + e] + (float)xx[j][2 + e] * INV_LOSC;
                float yy = yt[jj].x;
                l0[jj] = f0 * (sa0 * sbc[jj]) - yy;
                l1[jj] = f1 * (sa1 * sbc[jj]) - yy;
            }
        row_update(st0, l0, yt);
        row_update(st1, l1, yt);

        if (++stage == NSTAGE) { stage = 0; phase ^= 1; }
    }

    // ---- merge across quad (lanes sharing the same rows), write out ----
    row_merge(st0, 1); row_merge(st0, 2);
    row_merge(st1, 1); row_merge(st1, 2);

    if (q == 0) {
        size_t base = (size_t)b * 3 * NN;
        int na = n0 + wid * 16 + r;
        int nb = na + 8;
        float ia = 1.f / st0.s, ib = 1.f / st1.s;
        out[base + na] = st0.o0 * ia;
        out[base + NN + na] = st0.o1 * ia;
        out[base + 2 * NN + na] = st0.o2 * ia;
        out[base + nb] = st1.o0 * ib;
        out[base + NN + nb] = st1.o1 * ib;
        out[base + 2 * NN + nb] = st1.o2 * ib;
    }
}

extern "C" void kernel_launch(void* const* d_in, const int* in_sizes, int n_in,
                              void* d_out, int out_size) {
    // inputs per metadata: [0]=src (unused), [1]=tgt, [2]=src_emb, [3]=tgt_emb
    const float* tgt     = (const float*)d_in[1];
    const float* src_emb = (const float*)d_in[2];
    const float* tgt_emb = (const float*)d_in[3];
    float* out = (float*)d_out;

    cudaFuncSetAttribute(convB_kernel,
                         cudaFuncAttributeMaxDynamicSharedMemorySize, CONVB_SMEM);
    cudaFuncSetAttribute(corr_mma_kernel,
                         cudaFuncAttributeMaxDynamicSharedMemorySize, SMEM_MAIN);

    sa_kernel<<<dim3(NN / 256, BB), 256>>>(src_emb);
    convB_kernel<<<dim3(NMT, BB), 256, CONVB_SMEM>>>(tgt_emb, tgt);
    corr_mma_kernel<<<dim3(NN / TN, BB), 256, SMEM_MAIN>>>(src_emb, out);
}

// round 15
// speedup vs baseline: 3.1996x; 3.1996x over previous
#include <cuda_runtime.h>
#include <cuda_fp16.h>
#include <cstdint>

#define BB 4
#define DD 256
#define NN 4096
#define MM 4096
#define TN 128            // n rows per CTA
#define TM 32             // m cols per tile
#define NMT (MM / TM)     // 128 m-tiles
#define NSTAGE 3
#define L2E 1.4426950408889634f

#define ROW_BYTES 512     // 256 fp16, XOR-swizzled chunks (conflict-free for ldmatrix)
#define B_HALF (TM * ROW_BYTES)          // 16384
#define B_BLOB (2 * B_HALF)              // 32768 (hi then lo)
#define A_HALF (TN * ROW_BYTES)          // 65536

__device__ __align__(16) unsigned char g_B[BB * NMT * B_BLOB];  // 16MB
__device__ __align__(16) float4 g_ytg[BB * MM];                 // (yy*log2e, t0,t1,t2)

// ---------------- helpers ----------------
__device__ __forceinline__ uint32_t smem_u32(const void* p) {
    uint32_t a;
    asm("{ .reg .u64 t; cvta.to.shared.u64 t, %1; cvt.u32.u64 %0, t; }"
        : "=r"(a) : "l"(p));
    return a;
}

#define MBARRIER_INIT(mbar, cnt) \
    asm volatile("mbarrier.init.shared.b64 [%0], %1;" \
                 :: "r"((uint32_t)(mbar)), "r"((uint32_t)(cnt)) : "memory")
#define MBARRIER_EXPECT_TX(mbar, bytes) \
    asm volatile("mbarrier.arrive.expect_tx.shared.b64 _, [%0], %1;" \
                 :: "r"((uint32_t)(mbar)), "r"((uint32_t)(bytes)) : "memory")
#define MBARRIER_ARRIVE(mbar) \
    asm volatile("mbarrier.arrive.shared.b64 _, [%0];" \
                 :: "r"((uint32_t)(mbar)) : "memory")
#define MBARRIER_WAIT_PARITY(mbar, ph) do {                                    \
    uint32_t _m = (uint32_t)(mbar); uint32_t _p = (uint32_t)(ph);               \
    asm volatile(                                                               \
        "{\n\t.reg .pred P1;\n\t"                                               \
        "WL_%=:\n\t"                                                            \
        "mbarrier.try_wait.parity.acquire.cta.shared::cta.b64 P1, [%0], %1, 0x989680;\n\t" \
        "@P1 bra.uni WD_%=;\n\t"                                                \
        "bra.uni WL_%=;\n\t"                                                    \
        "WD_%=:\n\t}"                                                           \
        :: "r"(_m), "r"(_p) : "memory");                                        \
} while (0)

__device__ __forceinline__ void bulk_g2s(uint32_t dst_smem, const void* src,
                                         uint32_t bytes, uint32_t mbar) {
    asm volatile(
        "cp.async.bulk.shared::cluster.global.mbarrier::complete_tx::bytes [%0], [%1], %2, [%3];"
        :: "r"(dst_smem), "l"(src), "r"(bytes), "r"(mbar) : "memory");
}

__device__ __forceinline__ float ex2(float x) {
    float r;
    asm("ex2.approx.f32 %0, %1;" : "=f"(r) : "f"(x));
    return r;
}

#define LDSM_X4(r, addr) \
    asm volatile("ldmatrix.sync.aligned.m8n8.x4.shared.b16 {%0,%1,%2,%3}, [%4];" \
                 : "=r"((r)[0]), "=r"((r)[1]), "=r"((r)[2]), "=r"((r)[3]) \
                 : "r"(addr))

// fp16 inputs, fp32 accumulate (main hi*hi pass)
__device__ __forceinline__ void mma_f32acc(float (&c)[4],
                                           const uint32_t (&a)[4],
                                           uint32_t b0, uint32_t b1) {
    asm volatile(
        "mma.sync.aligned.m16n8k16.row.col.f32.f16.f16.f32 "
        "{%0,%1,%2,%3}, {%4,%5,%6,%7}, {%8,%9}, {%0,%1,%2,%3};"
        : "+f"(c[0]), "+f"(c[1]), "+f"(c[2]), "+f"(c[3])
        : "r"(a[0]), "r"(a[1]), "r"(a[2]), "r"(a[3]), "r"(b0), "r"(b1));
}

// fp16 inputs, fp16 accumulate (small cross terms) — possibly double-rate
__device__ __forceinline__ void mma_f16acc(uint32_t (&c)[2],
                                           const uint32_t (&a)[4],
                                           uint32_t b0, uint32_t b1) {
    asm volatile(
        "mma.sync.aligned.m16n8k16.row.col.f16.f16.f16.f16 "
        "{%0,%1}, {%2,%3,%4,%5}, {%6,%7}, {%0,%1};"
        : "+r"(c[0]), "+r"(c[1])
        : "r"(a[0]), "r"(a[1]), "r"(a[2]), "r"(a[3]), "r"(b0), "r"(b1));
}

__device__ __forceinline__ void split_pair(float f0, float f1,
                                           uint32_t& hi, uint32_t& lo) {
    __half h0 = __float2half_rn(f0);
    __half h1 = __float2half_rn(f1);
    __half l0 = __float2half_rn(f0 - __half2float(h0));
    __half l1 = __float2half_rn(f1 - __half2float(h1));
    hi = (uint32_t)__half_as_ushort(h0) | ((uint32_t)__half_as_ushort(h1) << 16);
    lo = (uint32_t)__half_as_ushort(l0) | ((uint32_t)__half_as_ushort(l1) << 16);
}

// ======= Kernel 1: tgt_emb -> swizzled fp16 hi/lo blobs (SMEM image) + ytg =======
#define CV_PAD 264
#define CONVB_SMEM ((TM * CV_PAD + TM) * 4)

__global__ void __launch_bounds__(256)
convB_kernel(const float* __restrict__ tgt_emb, const float* __restrict__ tgt) {
    extern __shared__ float cs[];          // [TM][CV_PAD] transpose stage
    float* syy = cs + TM * CV_PAD;
    const int tid = threadIdx.x;
    const int b = blockIdx.y, mt = blockIdx.x, m0 = mt * TM;

    if (tid < TM) syy[tid] = 0.f;
    __syncthreads();

    const float* g = tgt_emb + (size_t)b * DD * MM + m0;
    for (int i = tid; i < DD * TM; i += 256) {
        int d = i >> 5, m = i & 31;
        cs[m * CV_PAD + d] = g[(size_t)d * MM + m];
    }
    __syncthreads();

    unsigned char* outh = g_B + (size_t)(b * NMT + mt) * B_BLOB;
    unsigned char* outl = outh + B_HALF;

    for (int i = tid; i < TM * 32; i += 256) {   // task = (m-row, 16B chunk kg)
        int m = i >> 5, kg = i & 31;
        const float* p = cs + m * CV_PAD + kg * 8;
        float4 v0 = *(const float4*)(p);
        float4 v1 = *(const float4*)(p + 4);
        float part = v0.x * v0.x + v0.y * v0.y + v0.z * v0.z + v0.w * v0.w
                   + v1.x * v1.x + v1.y * v1.y + v1.z * v1.z + v1.w * v1.w;
        atomicAdd(&syy[m], part);

        uint4 hq, lq;
        split_pair(v0.x, v0.y, hq.x, lq.x);
        split_pair(v0.z, v0.w, hq.y, lq.y);
        split_pair(v1.x, v1.y, hq.z, lq.z);
        split_pair(v1.z, v1.w, hq.w, lq.w);

        int byte = m * ROW_BYTES + ((kg ^ (m & 7)) << 4);  // XOR swizzle
        *(uint4*)(outh + byte) = hq;
        *(uint4*)(outl + byte) = lq;
    }
    __syncthreads();
    if (tid < TM) {
        int m = m0 + tid;
        float4 v;
        v.x = L2E * syy[tid];
        v.y = tgt[(size_t)b * 3 * MM + m];
        v.z = tgt[(size_t)b * 3 * MM + MM + m];
        v.w = tgt[(size_t)b * 3 * MM + 2 * MM + m];
        g_ytg[b * MM + m] = v;
    }
}

// ======= Kernel 2: fused HMMA GEMM, A-in-regs, cross terms in f16-acc =======
// SMEM: mbar full/empty x3 @0..47, ytg 3x512 @64, A @1664, B stages @132736
#define SM_YTG 64
#define SM_A   1664
#define SM_B   (SM_A + 2 * A_HALF)              // 132736
#define SMEM_MAIN (SM_B + NSTAGE * B_BLOB)      // 231040

struct RowState { float m, s, o0, o1, o2; };

__device__ __forceinline__ void row_update(RowState& st, const float (&lg)[8],
                                           const float4 (&yt)[8]) {
    float tmax = lg[0];
#pragma unroll
    for (int j = 1; j < 8; ++j) tmax = fmaxf(tmax, lg[j]);
    float nm = fmaxf(st.m, tmax);
    float corr = ex2(st.m - nm);
    st.m = nm;
    float ls = 0.f, a0 = 0.f, a1 = 0.f, a2 = 0.f;
#pragma unroll
    for (int j = 0; j < 8; ++j) {
        float p = ex2(lg[j] - nm);
        ls += p;
        a0 += p * yt[j].y;
        a1 += p * yt[j].z;
        a2 += p * yt[j].w;
    }
    st.s = st.s * corr + ls;
    st.o0 = st.o0 * corr + a0;
    st.o1 = st.o1 * corr + a1;
    st.o2 = st.o2 * corr + a2;
}

__device__ __forceinline__ void row_merge(RowState& st, int off) {
    float om = __shfl_xor_sync(0xffffffffu, st.m, off);
    float os = __shfl_xor_sync(0xffffffffu, st.s, off);
    float g0 = __shfl_xor_sync(0xffffffffu, st.o0, off);
    float g1 = __shfl_xor_sync(0xffffffffu, st.o1, off);
    float g2 = __shfl_xor_sync(0xffffffffu, st.o2, off);
    float nm = fmaxf(st.m, om);
    float ca = ex2(st.m - nm), cb = ex2(om - nm);
    st.m = nm;
    st.s = st.s * ca + os * cb;
    st.o0 = st.o0 * ca + g0 * cb;
    st.o1 = st.o1 * ca + g1 * cb;
    st.o2 = st.o2 * ca + g2 * cb;
}

__global__ void __launch_bounds__(256, 1)
corr_mma_kernel(const float* __restrict__ src_emb, float* __restrict__ out) {
    extern __shared__ __align__(16) unsigned char smraw[];
    const uint32_t sb = smem_u32(smraw);
    const int tid = threadIdx.x;
    const int wid = tid >> 5;
    const int lane = tid & 31;
    const int b = blockIdx.y;
    const int n0 = blockIdx.x * TN;

    if (tid == 0) {
#pragma unroll
        for (int s = 0; s < NSTAGE; ++s) {
            MBARRIER_INIT(sb + s * 16, 1);       // full
            MBARRIER_INIT(sb + s * 16 + 8, 8);   // empty: 8 warp arrivals
        }
    }
    __syncthreads();

    const unsigned char* gB = g_B + (size_t)b * NMT * B_BLOB;
    const float4* gY = g_ytg + b * MM;

    // kick off loads for tiles 0..2
    if (tid == 0) {
#pragma unroll
        for (int s = 0; s < NSTAGE; ++s) {
            MBARRIER_EXPECT_TX(sb + s * 16, B_BLOB + 512);
            bulk_g2s(sb + SM_B + s * B_BLOB, gB + (size_t)s * B_BLOB, B_BLOB, sb + s * 16);
            bulk_g2s(sb + SM_YTG + s * 512, gY + s * TM, 512, sb + s * 16);
        }
    }

    // ---- convert A (src_emb rows n0..n0+127, scaled by 2*log2e) into SMEM ----
    {
        unsigned char* Ah = smraw + SM_A;
        unsigned char* Al = Ah + A_HALF;
        const float* gA = src_emb + (size_t)b * DD * NN + n0;
        const float sc = 2.0f * L2E;
        for (int i = tid; i < DD * TN / 2; i += 256) {
            int n = i & 127;
            int dp = i >> 7;             // 0..127, covers d = 2dp, 2dp+1
            float v0 = sc * gA[(size_t)(2 * dp) * NN + n];
            float v1 = sc * gA[(size_t)(2 * dp + 1) * NN + n];
            uint32_t hi, lo;
            split_pair(v0, v1, hi, lo);
            int byte = n * ROW_BYTES + (((dp >> 2) ^ (n & 7)) << 4) + (dp & 3) * 4;
            *(uint32_t*)(Ah + byte) = hi;
            *(uint32_t*)(Al + byte) = lo;
        }
    }
    __syncthreads();

    // ---- A fragments -> registers (persistent across all 128 tiles) ----
    const int q = lane & 3;
    const int r = lane >> 2;
    const uint32_t rowA = wid * 16 + ((lane >> 3) & 1) * 8 + (lane & 7);
    const uint32_t aBase = sb + SM_A + rowA * ROW_BYTES;
    const uint32_t hcA = (uint32_t)(lane >> 4);       // 0/1: k-chunk half
    const uint32_t rswA = rowA & 7;

    uint32_t ahr[16][4], alr[16][4];
#pragma unroll
    for (int s = 0; s < 16; ++s) {
        const uint32_t swA = ((2 * s + hcA) ^ rswA) << 4;
        LDSM_X4(ahr[s], aBase + swA);
        LDSM_X4(alr[s], aBase + swA + A_HALF);
    }

    // B ldmatrix lane bases
    const uint32_t rB0 = (uint32_t)((lane >> 4) * 8 + (lane & 7));  // rows 0..15
    const uint32_t bBase0 = rB0 * ROW_BYTES;
    const uint32_t hcB = (uint32_t)((lane >> 3) & 1);
    const uint32_t rswB = rB0 & 7;

    RowState st0 = {-1e30f, 0.f, 0.f, 0.f, 0.f};
    RowState st1 = {-1e30f, 0.f, 0.f, 0.f, 0.f};

    const float4* ytg_s = (const float4*)(smraw + SM_YTG);

    int stage = 0, phase = 0;
    for (int t = 0; t < NMT; ++t) {
        MBARRIER_WAIT_PARITY(sb + stage * 16, phase);

        const uint32_t bb = sb + SM_B + stage * B_BLOB;

        float acc[4][4];         // hi*hi in f32
        uint32_t cac[4][2];      // cross terms in f16x2
#pragma unroll
        for (int j = 0; j < 4; ++j) {
#pragma unroll
            for (int e = 0; e < 4; ++e) acc[j][e] = 0.f;
            cac[j][0] = 0u; cac[j][1] = 0u;
        }

#pragma unroll
        for (int s = 0; s < 16; ++s) {
            const uint32_t swB = ((2 * s + hcB) ^ rswB) << 4;
            uint32_t bh[4], bh2[4], bl[4], bl2[4];
            LDSM_X4(bh, bb + bBase0 + swB);
            LDSM_X4(bh2, bb + bBase0 + swB + 16 * ROW_BYTES);
            LDSM_X4(bl, bb + bBase0 + swB + B_HALF);
            LDSM_X4(bl2, bb + bBase0 + swB + B_HALF + 16 * ROW_BYTES);
            // hi*hi -> f32 acc
            mma_f32acc(acc[0], ahr[s], bh[0], bh[1]);
            mma_f32acc(acc[1], ahr[s], bh[2], bh[3]);
            mma_f32acc(acc[2], ahr[s], bh2[0], bh2[1]);
            mma_f32acc(acc[3], ahr[s], bh2[2], bh2[3]);
            // lo*hi -> f16 acc (small)
            mma_f16acc(cac[0], alr[s], bh[0], bh[1]);
            mma_f16acc(cac[1], alr[s], bh[2], bh[3]);
            mma_f16acc(cac[2], alr[s], bh2[0], bh2[1]);
            mma_f16acc(cac[3], alr[s], bh2[2], bh2[3]);
            // hi*lo -> f16 acc (small)
            mma_f16acc(cac[0], ahr[s], bl[0], bl[1]);
            mma_f16acc(cac[1], ahr[s], bl[2], bl[3]);
            mma_f16acc(cac[2], ahr[s], bl2[0], bl2[1]);
            mma_f16acc(cac[3], ahr[s], bl2[2], bl2[3]);
        }

        // grab this tile's (yy, t0..t2) for my 8 cols before releasing the buffer
        float4 yt[8];
#pragma unroll
        for (int j = 0; j < 4; ++j)
#pragma unroll
            for (int e = 0; e < 2; ++e)
                yt[j * 2 + e] = ytg_s[stage * 32 + j * 8 + q * 2 + e];

        if (lane == 0) MBARRIER_ARRIVE(sb + stage * 16 + 8);  // warp done with buffer

        // producer: refill this stage for tile t+3 once all warps released it
        if (tid == 0 && t + NSTAGE < NMT) {
            MBARRIER_WAIT_PARITY(sb + stage * 16 + 8, phase);
            MBARRIER_EXPECT_TX(sb + stage * 16, B_BLOB + 512);
            bulk_g2s(sb + SM_B + stage * B_BLOB, gB + (size_t)(t + NSTAGE) * B_BLOB,
                     B_BLOB, sb + stage * 16);
            bulk_g2s(sb + SM_YTG + stage * 512, gY + (t + NSTAGE) * TM, 512,
                     sb + stage * 16);
        }

        // ---- per-thread online softmax (rows r0 = wid*16+r, r1 = +8) ----
        float l0[8], l1[8];
#pragma unroll
        for (int j = 0; j < 4; ++j) {
            __half2 c0 = *reinterpret_cast<__half2*>(&cac[j][0]);  // row r, cols (0,1)
            __half2 c1 = *reinterpret_cast<__half2*>(&cac[j][1]);  // row r+8, cols (0,1)
            float2 f0 = __half22float2(c0);
            float2 f1 = __half22float2(c1);
            float yy0 = yt[j * 2].x;
            float yy1 = yt[j * 2 + 1].x;
            l0[j * 2]     = acc[j][0] + f0.x - yy0;
            l0[j * 2 + 1] = acc[j][1] + f0.y - yy1;
            l1[j * 2]     = acc[j][2] + f1.x - yy0;
            l1[j * 2 + 1] = acc[j][3] + f1.y - yy1;
        }
        row_update(st0, l0, yt);
        row_update(st1, l1, yt);

        if (++stage == NSTAGE) { stage = 0; phase ^= 1; }
    }

    // ---- merge across quad (lanes sharing the same rows), write out ----
    row_merge(st0, 1); row_merge(st0, 2);
    row_merge(st1, 1); row_merge(st1, 2);

    if (q == 0) {
        size_t base = (size_t)b * 3 * NN;
        int na = n0 + wid * 16 + r;
        int nb = na + 8;
        float ia = 1.f / st0.s, ib = 1.f / st1.s;
        out[base + na] = st0.o0 * ia;
        out[base + NN + na] = st0.o1 * ia;
        out[base + 2 * NN + na] = st0.o2 * ia;
        out[base + nb] = st1.o0 * ib;
        out[base + NN + nb] = st1.o1 * ib;
        out[base + 2 * NN + nb] = st1.o2 * ib;
    }
}

extern "C" void kernel_launch(void* const* d_in, const int* in_sizes, int n_in,
                              void* d_out, int out_size) {
    // inputs per metadata: [0]=src (unused), [1]=tgt, [2]=src_emb, [3]=tgt_emb
    const float* tgt     = (const float*)d_in[1];
    const float* src_emb = (const float*)d_in[2];
    const float* tgt_emb = (const float*)d_in[3];
    float* out = (float*)d_out;

    cudaFuncSetAttribute(convB_kernel,
                         cudaFuncAttributeMaxDynamicSharedMemorySize, CONVB_SMEM);
    cudaFuncSetAttribute(corr_mma_kernel,
                         cudaFuncAttributeMaxDynamicSharedMemorySize, SMEM_MAIN);

    convB_kernel<<<dim3(NMT, BB), 256, CONVB_SMEM>>>(tgt_emb, tgt);
    corr_mma_kernel<<<dim3(NN / TN, BB), 256, SMEM_MAIN>>>(src_emb, out);
}

// round 17
// speedup vs baseline: 3.5249x; 1.1017x over previous
#include <cuda_runtime.h>
#include <cuda_bf16.h>
#include <cstdint>

#define BB 4
#define DD 256
#define NN 4096
#define MM 4096
#define TN 128            // n rows per n-block
#define TM 32             // m cols per tile
#define NMT (MM / TM)     // 128 m-tiles
#define NBLK 32           // n-blocks per batch
#define TOTAL (BB * NBLK * NMT)   // 16384 tasks
#define NCTA 152          // GB300 SM count (persistent grid)
#define NSTAGE 3
#define L2E 1.4426950408889634f

#define ROW_BYTES 512     // 256 bf16, XOR-swizzled chunks (conflict-free for ldmatrix)
#define B_HALF (TM * ROW_BYTES)          // 16384
#define B_BLOB (2 * B_HALF)              // 32768 (hi then lo)
#define A_HALF (TN * ROW_BYTES)          // 65536

__device__ __align__(16) unsigned char g_B[BB * NMT * B_BLOB];  // 16MB
__device__ __align__(16) float4 g_ytg[BB * MM];                 // (yy*log2e, t0,t1,t2)
__device__ __align__(16) float g_part[128 * 4 * 128 * 5];       // partials (nb,slot,row,5)

// ---------------- helpers ----------------
__device__ __forceinline__ uint32_t smem_u32(const void* p) {
    uint32_t a;
    asm("{ .reg .u64 t; cvta.to.shared.u64 t, %1; cvt.u32.u64 %0, t; }"
        : "=r"(a) : "l"(p));
    return a;
}

#define MBARRIER_INIT(mbar, cnt) \
    asm volatile("mbarrier.init.shared.b64 [%0], %1;" \
                 :: "r"((uint32_t)(mbar)), "r"((uint32_t)(cnt)) : "memory")
#define MBARRIER_EXPECT_TX(mbar, bytes) \
    asm volatile("mbarrier.arrive.expect_tx.shared.b64 _, [%0], %1;" \
                 :: "r"((uint32_t)(mbar)), "r"((uint32_t)(bytes)) : "memory")
#define MBARRIER_ARRIVE(mbar) \
    asm volatile("mbarrier.arrive.shared.b64 _, [%0];" \
                 :: "r"((uint32_t)(mbar)) : "memory")
#define MBARRIER_WAIT_PARITY(mbar, ph) do {                                    \
    uint32_t _m = (uint32_t)(mbar); uint32_t _p = (uint32_t)(ph);               \
    asm volatile(                                                               \
        "{\n\t.reg .pred P1;\n\t"                                               \
        "WL_%=:\n\t"                                                            \
        "mbarrier.try_wait.parity.acquire.cta.shared::cta.b64 P1, [%0], %1, 0x989680;\n\t" \
        "@P1 bra.uni WD_%=;\n\t"                                                \
        "bra.uni WL_%=;\n\t"                                                    \
        "WD_%=:\n\t}"                                                           \
        :: "r"(_m), "r"(_p) : "memory");                                        \
} while (0)

__device__ __forceinline__ void bulk_g2s(uint32_t dst_smem, const void* src,
                                         uint32_t bytes, uint32_t mbar) {
    asm volatile(
        "cp.async.bulk.shared::cluster.global.mbarrier::complete_tx::bytes [%0], [%1], %2, [%3];"
        :: "r"(dst_smem), "l"(src), "r"(bytes), "r"(mbar) : "memory");
}

__device__ __forceinline__ float ex2(float x) {
    float r;
    asm("ex2.approx.f32 %0, %1;" : "=f"(r) : "f"(x));
    return r;
}

#define LDSM_X4(r, addr) \
    asm volatile("ldmatrix.sync.aligned.m8n8.x4.shared.b16 {%0,%1,%2,%3}, [%4];" \
                 : "=r"((r)[0]), "=r"((r)[1]), "=r"((r)[2]), "=r"((r)[3]) \
                 : "r"(addr))

__device__ __forceinline__ void mma_bf16(float (&c)[4],
                                         const uint32_t (&a)[4],
                                         uint32_t b0, uint32_t b1) {
    asm volatile(
        "mma.sync.aligned.m16n8k16.row.col.f32.bf16.bf16.f32 "
        "{%0,%1,%2,%3}, {%4,%5,%6,%7}, {%8,%9}, {%0,%1,%2,%3};"
        : "+f"(c[0]), "+f"(c[1]), "+f"(c[2]), "+f"(c[3])
        : "r"(a[0]), "r"(a[1]), "r"(a[2]), "r"(a[3]), "r"(b0), "r"(b1));
}

__device__ __forceinline__ void split_pair(float f0, float f1,
                                           uint32_t& hi, uint32_t& lo) {
    __nv_bfloat16 h0 = __float2bfloat16(f0);
    __nv_bfloat16 h1 = __float2bfloat16(f1);
    __nv_bfloat16 l0 = __float2bfloat16(f0 - __bfloat162float(h0));
    __nv_bfloat16 l1 = __float2bfloat16(f1 - __bfloat162float(h1));
    hi = (uint32_t)__bfloat16_as_ushort(h0) | ((uint32_t)__bfloat16_as_ushort(h1) << 16);
    lo = (uint32_t)__bfloat16_as_ushort(l0) | ((uint32_t)__bfloat16_as_ushort(l1) << 16);
}

// CTA index owning global task g (inverse of the floor partition)
__device__ __forceinline__ int cta_of(int g) {
    return (int)(((long long)(g + 1) * NCTA - 1) / TOTAL);
}

// ======= Kernel 1: tgt_emb -> swizzled bf16 hi/lo blobs (SMEM image) + ytg =======
#define CV_PAD 264
#define CONVB_SMEM ((TM * CV_PAD + TM) * 4)

__global__ void __launch_bounds__(256)
convB_kernel(const float* __restrict__ tgt_emb, const float* __restrict__ tgt) {
    extern __shared__ float cs[];          // [TM][CV_PAD] transpose stage
    float* syy = cs + TM * CV_PAD;
    const int tid = threadIdx.x;
    const int b = blockIdx.y, mt = blockIdx.x, m0 = mt * TM;

    if (tid < TM) syy[tid] = 0.f;
    __syncthreads();

    const float* g = tgt_emb + (size_t)b * DD * MM + m0;
    for (int i = tid; i < DD * TM; i += 256) {
        int d = i >> 5, m = i & 31;
        cs[m * CV_PAD + d] = g[(size_t)d * MM + m];
    }
    __syncthreads();

    unsigned char* outh = g_B + (size_t)(b * NMT + mt) * B_BLOB;
    unsigned char* outl = outh + B_HALF;

    for (int i = tid; i < TM * 32; i += 256) {   // task = (m-row, 16B chunk kg)
        int m = i >> 5, kg = i & 31;
        const float* p = cs + m * CV_PAD + kg * 8;
        float4 v0 = *(const float4*)(p);
        float4 v1 = *(const float4*)(p + 4);
        float part = v0.x * v0.x + v0.y * v0.y + v0.z * v0.z + v0.w * v0.w
                   + v1.x * v1.x + v1.y * v1.y + v1.z * v1.z + v1.w * v1.w;
        atomicAdd(&syy[m], part);

        uint4 hq, lq;
        split_pair(v0.x, v0.y, hq.x, lq.x);
        split_pair(v0.z, v0.w, hq.y, lq.y);
        split_pair(v1.x, v1.y, hq.z, lq.z);
        split_pair(v1.z, v1.w, hq.w, lq.w);

        int byte = m * ROW_BYTES + ((kg ^ (m & 7)) << 4);  // XOR swizzle
        *(uint4*)(outh + byte) = hq;
        *(uint4*)(outl + byte) = lq;
    }
    __syncthreads();
    if (tid < TM) {
        int m = m0 + tid;
        float4 v;
        v.x = L2E * syy[tid];
        v.y = tgt[(size_t)b * 3 * MM + m];
        v.z = tgt[(size_t)b * 3 * MM + MM + m];
        v.w = tgt[(size_t)b * 3 * MM + 2 * MM + m];
        g_ytg[b * MM + m] = v;
    }
}

// ======= Kernel 2: persistent fused HMMA GEMM over balanced task ranges =======
// SMEM: mbar full/empty x3 @0..47, ytg 3x512 @64, A @1664, B stages @132736
#define SM_YTG 64
#define SM_A   1664
#define SM_B   (SM_A + 2 * A_HALF)              // 132736
#define SMEM_MAIN (SM_B + NSTAGE * B_BLOB)      // 231040

struct RowState { float m, s, o0, o1, o2; };

__device__ __forceinline__ void row_update(RowState& st, const float (&lg)[8],
                                           const float4 (&yt)[8]) {
    float tmax = lg[0];
#pragma unroll
    for (int j = 1; j < 8; ++j) tmax = fmaxf(tmax, lg[j]);
    float nm = fmaxf(st.m, tmax);
    float corr = ex2(st.m - nm);
    st.m = nm;
    float ls = 0.f, a0 = 0.f, a1 = 0.f, a2 = 0.f;
#pragma unroll
    for (int j = 0; j < 8; ++j) {
        float p = ex2(lg[j] - nm);
        ls += p;
        a0 += p * yt[j].y;
        a1 += p * yt[j].z;
        a2 += p * yt[j].w;
    }
    st.s = st.s * corr + ls;
    st.o0 = st.o0 * corr + a0;
    st.o1 = st.o1 * corr + a1;
    st.o2 = st.o2 * corr + a2;
}

__device__ __forceinline__ void row_merge(RowState& st, int off) {
    float om = __shfl_xor_sync(0xffffffffu, st.m, off);
    float os = __shfl_xor_sync(0xffffffffu, st.s, off);
    float g0 = __shfl_xor_sync(0xffffffffu, st.o0, off);
    float g1 = __shfl_xor_sync(0xffffffffu, st.o1, off);
    float g2 = __shfl_xor_sync(0xffffffffu, st.o2, off);
    float nm = fmaxf(st.m, om);
    float ca = ex2(st.m - nm), cb = ex2(om - nm);
    st.m = nm;
    st.s = st.s * ca + os * cb;
    st.o0 = st.o0 * ca + g0 * cb;
    st.o1 = st.o1 * ca + g1 * cb;
    st.o2 = st.o2 * ca + g2 * cb;
}

__global__ void __launch_bounds__(256, 1)
corr_mma_kernel(const float* __restrict__ src_emb) {
    extern __shared__ __align__(16) unsigned char smraw[];
    const uint32_t sb = smem_u32(smraw);
    const int tid = threadIdx.x;
    const int wid = tid >> 5;
    const int lane = tid & 31;
    const int c = blockIdx.x;
    const int gstart = (int)((long long)c * TOTAL / NCTA);
    const int gend = (int)((long long)(c + 1) * TOTAL / NCTA);
    const int nloc = gend - gstart;

    if (tid == 0) {
#pragma unroll
        for (int s = 0; s < NSTAGE; ++s) {
            MBARRIER_INIT(sb + s * 16, 1);       // full
            MBARRIER_INIT(sb + s * 16 + 8, 8);   // empty: 8 warp arrivals
        }
    }
    __syncthreads();

    // ring prologue: fill first min(3, nloc) tasks
    if (tid == 0) {
        int nf = nloc < NSTAGE ? nloc : NSTAGE;
        for (int s = 0; s < nf; ++s) {
            int gg = gstart + s;
            int bb_ = gg >> 12, mtt = gg & 127;
            MBARRIER_EXPECT_TX(sb + s * 16, B_BLOB + 512);
            bulk_g2s(sb + SM_B + s * B_BLOB,
                     g_B + (size_t)(bb_ * NMT + mtt) * B_BLOB, B_BLOB, sb + s * 16);
            bulk_g2s(sb + SM_YTG + s * 512,
                     (const void*)(g_ytg + (size_t)bb_ * MM + mtt * TM), 512, sb + s * 16);
        }
    }

    const int q = lane & 3;
    const int r = lane >> 2;
    const uint32_t rowA = wid * 16 + ((lane >> 3) & 1) * 8 + (lane & 7);
    const uint32_t aBase = sb + SM_A + rowA * ROW_BYTES;
    const uint32_t hcA = (uint32_t)(lane >> 4);
    const uint32_t rswA = rowA & 7;
    const uint32_t rB0 = (uint32_t)((lane >> 4) * 8 + (lane & 7));
    const uint32_t bBase0 = rB0 * ROW_BYTES;
    const uint32_t hcB = (uint32_t)((lane >> 3) & 1);
    const uint32_t rswB = rB0 & 7;

    const float4* ytg_s = (const float4*)(smraw + SM_YTG);

    int stage = 0, phase = 0;
    int lidx = 0;
    int g = gstart;

    while (g < gend) {
        const int nb = g >> 7;
        const int mt0 = g & 127;
        int cnt = 128 - mt0;
        if (cnt > gend - g) cnt = gend - g;
        const int b = nb >> 5;
        const int n0 = (nb & (NBLK - 1)) * TN;

        // ---- stage A (this n-block) into SMEM, scaled by 2*log2e ----
        {
            unsigned char* Ah = smraw + SM_A;
            unsigned char* Al = Ah + A_HALF;
            const float* gA = src_emb + (size_t)b * DD * NN + n0;
            const float sc = 2.0f * L2E;
            for (int i = tid; i < DD * TN / 2; i += 256) {
                int n = i & 127;
                int dp = i >> 7;
                float v0 = sc * gA[(size_t)(2 * dp) * NN + n];
                float v1 = sc * gA[(size_t)(2 * dp + 1) * NN + n];
                uint32_t hi, lo;
                split_pair(v0, v1, hi, lo);
                int byte = n * ROW_BYTES + (((dp >> 2) ^ (n & 7)) << 4) + (dp & 3) * 4;
                *(uint32_t*)(Ah + byte) = hi;
                *(uint32_t*)(Al + byte) = lo;
            }
        }
        __syncthreads();

        // ---- A fragments -> registers (persistent across this segment) ----
        uint32_t ahr[16][4], alr[16][4];
#pragma unroll
        for (int s = 0; s < 16; ++s) {
            const uint32_t swA = ((2 * s + hcA) ^ rswA) << 4;
            LDSM_X4(ahr[s], aBase + swA);
            LDSM_X4(alr[s], aBase + swA + A_HALF);
        }

        RowState st0 = {-1e30f, 0.f, 0.f, 0.f, 0.f};
        RowState st1 = {-1e30f, 0.f, 0.f, 0.f, 0.f};

        for (int t = 0; t < cnt; ++t, ++lidx) {
            MBARRIER_WAIT_PARITY(sb + stage * 16, phase);

            const uint32_t bb = sb + SM_B + stage * B_BLOB;

            float acc[4][4];
#pragma unroll
            for (int j = 0; j < 4; ++j)
#pragma unroll
                for (int e = 0; e < 4; ++e) acc[j][e] = 0.f;

#pragma unroll
            for (int s = 0; s < 16; ++s) {
                const uint32_t swB = ((2 * s + hcB) ^ rswB) << 4;
                uint32_t bh[4], bh2[4], bl[4], bl2[4];
                LDSM_X4(bh, bb + bBase0 + swB);
                LDSM_X4(bh2, bb + bBase0 + swB + 16 * ROW_BYTES);
                LDSM_X4(bl, bb + bBase0 + swB + B_HALF);
                LDSM_X4(bl2, bb + bBase0 + swB + B_HALF + 16 * ROW_BYTES);
                mma_bf16(acc[0], ahr[s], bh[0], bh[1]);
                mma_bf16(acc[1], ahr[s], bh[2], bh[3]);
                mma_bf16(acc[2], ahr[s], bh2[0], bh2[1]);
                mma_bf16(acc[3], ahr[s], bh2[2], bh2[3]);
                mma_bf16(acc[0], alr[s], bh[0], bh[1]);
                mma_bf16(acc[1], alr[s], bh[2], bh[3]);
                mma_bf16(acc[2], alr[s], bh2[0], bh2[1]);
                mma_bf16(acc[3], alr[s], bh2[2], bh2[3]);
                mma_bf16(acc[0], ahr[s], bl[0], bl[1]);
                mma_bf16(acc[1], ahr[s], bl[2], bl[3]);
                mma_bf16(acc[2], ahr[s], bl2[0], bl2[1]);
                mma_bf16(acc[3], ahr[s], bl2[2], bl2[3]);
            }

            // grab this tile's (yy, t0..t2) before releasing the buffer
            float4 yt[8];
#pragma unroll
            for (int j = 0; j < 4; ++j)
#pragma unroll
                for (int e = 0; e < 2; ++e)
                    yt[j * 2 + e] = ytg_s[stage * 32 + j * 8 + q * 2 + e];

            if (lane == 0) MBARRIER_ARRIVE(sb + stage * 16 + 8);

            // producer: refill this stage for local task lidx+3
            if (tid == 0 && lidx + NSTAGE < nloc) {
                int gg = gstart + lidx + NSTAGE;
                int bb_ = gg >> 12, mtt = gg & 127;
                MBARRIER_WAIT_PARITY(sb + stage * 16 + 8, phase);
                MBARRIER_EXPECT_TX(sb + stage * 16, B_BLOB + 512);
                bulk_g2s(sb + SM_B + stage * B_BLOB,
                         g_B + (size_t)(bb_ * NMT + mtt) * B_BLOB, B_BLOB, sb + stage * 16);
                bulk_g2s(sb + SM_YTG + stage * 512,
                         (const void*)(g_ytg + (size_t)bb_ * MM + mtt * TM), 512,
                         sb + stage * 16);
            }

            // ---- per-thread online softmax ----
            float l0[8], l1[8];
#pragma unroll
            for (int j = 0; j < 4; ++j)
#pragma unroll
                for (int e = 0; e < 2; ++e) {
                    float yy = yt[j * 2 + e].x;
                    l0[j * 2 + e] = acc[j][e] - yy;
                    l1[j * 2 + e] = acc[j][2 + e] - yy;
                }
            row_update(st0, l0, yt);
            row_update(st1, l1, yt);

            if (++stage == NSTAGE) { stage = 0; phase ^= 1; }
        }

        // ---- merge across quad, write PARTIAL state to scratch ----
        row_merge(st0, 1); row_merge(st0, 2);
        row_merge(st1, 1); row_merge(st1, 2);

        if (q == 0) {
            int slot = c - cta_of(nb << 7);
            int ra = wid * 16 + r;
            float* p = g_part + ((size_t)((nb * 4 + slot) * 128 + ra)) * 5;
            p[0] = st0.m; p[1] = st0.s; p[2] = st0.o0; p[3] = st0.o1; p[4] = st0.o2;
            float* p2 = g_part + ((size_t)((nb * 4 + slot) * 128 + ra + 8)) * 5;
            p2[0] = st1.m; p2[1] = st1.s; p2[2] = st1.o0; p2[3] = st1.o1; p2[4] = st1.o2;
        }

        g += cnt;
        __syncthreads();   // all warps done with A before next segment restages it
    }
}

// ======= Kernel 3: merge partials, normalize, write output =======
__global__ void __launch_bounds__(256)
combine_kernel(float* __restrict__ out) {
    int i = blockIdx.x * 256 + threadIdx.x;   // 0..16383
    int nb = i >> 7, rr = i & 127;
    int c0 = cta_of(nb << 7);
    int c1 = cta_of((nb << 7) + 127);
    const float* p = g_part + ((size_t)((nb * 4) * 128 + rr)) * 5;
    float m = p[0], s = p[1], o0 = p[2], o1 = p[3], o2 = p[4];
    for (int sl = 1; sl <= c1 - c0; ++sl) {
        const float* p2 = g_part + ((size_t)((nb * 4 + sl) * 128 + rr)) * 5;
        float m2 = p2[0];
        float nm = fmaxf(m, m2);
        float ca = ex2(m - nm), cb = ex2(m2 - nm);
        s = s * ca + p2[1] * cb;
        o0 = o0 * ca + p2[2] * cb;
        o1 = o1 * ca + p2[3] * cb;
        o2 = o2 * ca + p2[4] * cb;
        m = nm;
    }
    int b = nb >> 5;
    int n = ((nb & (NBLK - 1)) << 7) + rr;
    float inv = 1.f / s;
    size_t base = (size_t)b * 3 * NN;
    out[base + n] = o0 * inv;
    out[base + NN + n] = o1 * inv;
    out[base + 2 * NN + n] = o2 * inv;
}

extern "C" void kernel_launch(void* const* d_in, const int* in_sizes, int n_in,
                              void* d_out, int out_size) {
    // inputs per metadata: [0]=src (unused), [1]=tgt, [2]=src_emb, [3]=tgt_emb
    const float* tgt     = (const float*)d_in[1];
    const float* src_emb = (const float*)d_in[2];
    const float* tgt_emb = (const float*)d_in[3];
    float* out = (float*)d_out;

    cudaFuncSetAttribute(convB_kernel,
                         cudaFuncAttributeMaxDynamicSharedMemorySize, CONVB_SMEM);
    cudaFuncSetAttribute(corr_mma_kernel,
                         cudaFuncAttributeMaxDynamicSharedMemorySize, SMEM_MAIN);

    convB_kernel<<<dim3(NMT, BB), 256, CONVB_SMEM>>>(tgt_emb, tgt);
    corr_mma_kernel<<<NCTA, 256, SMEM_MAIN>>>(src_emb);
    combine_kernel<<<TOTAL / 256, 256>>>(out);   // 64 blocks
}